// round 2
// baseline (speedup 1.0000x reference)
#include <cuda_runtime.h>

#define BB 32
#define SS 4096
#define CC 768
#define HH 12
#define DD 64
#define NCHUNK 22
#define SCHUNK 192

// ---- scratch (device globals; allocation is forbidden) ----
__device__ float g_wk[HH * CC];                                    // folded key weights
__device__ float g_sbias[HH];                                      // qh . bk
__device__ float g_mz[BB * NCHUNK * HH * 2];                       // per-chunk (max, expsum)
__device__ float g_ypart[(size_t)BB * NCHUNK * 2 * HH * CC];       // per (chunk,half) partial y
__device__ float g_y[BB * HH * CC];                                // combined y

typedef unsigned long long u64;

__device__ __forceinline__ u64 pk2(float a, float b) {
    u64 r; asm("mov.b64 %0,{%1,%2};" : "=l"(r) : "f"(a), "f"(b)); return r;
}
__device__ __forceinline__ float2 up2(u64 v) {
    float2 r; asm("mov.b64 {%0,%1},%2;" : "=f"(r.x), "=f"(r.y) : "l"(v)); return r;
}
__device__ __forceinline__ void ffma2(u64& d, u64 a, u64 b) {
    asm("fma.rn.f32x2 %0,%1,%2,%0;" : "+l"(d) : "l"(a), "l"(b));
}
__device__ __forceinline__ u64 vadd2(u64 a, u64 b) {
    u64 r; asm("add.rn.f32x2 %0,%1,%2;" : "=l"(r) : "l"(a), "l"(b)); return r;
}

// ================= prep: qh then wk, one block per head =================
__global__ __launch_bounds__(256) void k_prep(const float* __restrict__ probe,
                                              const float* __restrict__ Wq,
                                              const float* __restrict__ bq,
                                              const float* __restrict__ Wk,
                                              const float* __restrict__ bk) {
    int h = blockIdx.x, t = threadIdx.x;
    __shared__ float red[4][DD];
    __shared__ float qs[DD];
    int d = t & 63, part = t >> 6;
    float a = 0.f;
    for (int c = part; c < CC; c += 4)
        a = fmaf(probe[c], Wq[(size_t)c * CC + h * DD + d], a);
    red[part][d] = a;
    __syncthreads();
    if (t < DD)
        qs[t] = (red[0][t] + red[1][t] + red[2][t] + red[3][t] + bq[h * DD + t]) * 0.125f;
    __syncthreads();
    for (int c = t; c < CC; c += 256) {
        const float4* wr = (const float4*)(Wk + (size_t)c * CC + h * DD);
        float s = 0.f;
        #pragma unroll
        for (int j = 0; j < DD / 4; j++) {
            float4 wv = wr[j];
            const float4 qv = *(const float4*)(qs + 4 * j);
            s += wv.x * qv.x + wv.y * qv.y + wv.z * qv.z + wv.w * qv.w;
        }
        g_wk[h * CC + c] = s;
    }
    if (t == 0) {
        float s = 0.f;
        for (int d2 = 0; d2 < DD; d2++) s += bk[h * DD + d2] * qs[d2];
        g_sbias[h] = s;
    }
}

// ================= fused: scores + chunk softmax + weighted accumulate =================
// block = (chunk, batch), 192 threads.
__global__ __launch_bounds__(192) void k_fused(const float* __restrict__ x) {
    __shared__ float wks[HH * CC];          // 36 KB
    __shared__ float sc[HH][SCHUNK];        // 9 KB: scores -> exp weights
    __shared__ float sbs[HH];

    int t = threadIdx.x, ch = blockIdx.x, b = blockIdx.y;
    int s0 = ch * SCHUNK;
    for (int i = t; i < HH * CC; i += 192) wks[i] = g_wk[i];
    if (t < HH) sbs[t] = g_sbias[t];
    __syncthreads();

    int lane = t & 31, w = t >> 5, g = lane >> 3, q = lane & 7;
    const float* xb = x + (size_t)b * SS * CC;

    // ---- phase 1: scores. quad layout (8 lanes/row), R=4 rows per thread ----
    for (int pass = 0; pass < 2; pass++) {
        int lbase = pass * 96 + w * 16 + g;            // local row = lbase + 4k
        u64 acc[HH][4];
        #pragma unroll
        for (int h = 0; h < HH; h++)
            #pragma unroll
            for (int k = 0; k < 4; k++) acc[h][k] = 0ull;

        #pragma unroll 2
        for (int j = 0; j < 24; j++) {
            int c4 = j * 8 + q;
            ulonglong2 xv[4];
            #pragma unroll
            for (int k = 0; k < 4; k++) {
                int row = s0 + lbase + 4 * k;
                int rc = row < SS ? row : SS - 1;      // clamp; masked later
                xv[k] = *(const ulonglong2*)(xb + (size_t)rc * CC + c4 * 4);
            }
            #pragma unroll
            for (int h = 0; h < HH; h++) {
                ulonglong2 wv = *(const ulonglong2*)(wks + h * CC + c4 * 4);
                #pragma unroll
                for (int k = 0; k < 4; k++) {
                    ffma2(acc[h][k], xv[k].x, wv.x);
                    ffma2(acc[h][k], xv[k].y, wv.y);
                }
            }
        }
        #pragma unroll
        for (int h = 0; h < HH; h++) {
            #pragma unroll
            for (int k = 0; k < 4; k++) {
                u64 v = acc[h][k];
                v = vadd2(v, __shfl_xor_sync(0xffffffffu, v, 4));
                v = vadd2(v, __shfl_xor_sync(0xffffffffu, v, 2));
                v = vadd2(v, __shfl_xor_sync(0xffffffffu, v, 1));
                if (q == 0) {
                    int lr = lbase + 4 * k;
                    float2 f = up2(v);
                    sc[h][lr] = (s0 + lr < SS) ? (f.x + f.y + sbs[h]) : -1e30f;
                }
            }
        }
    }
    __syncthreads();

    // ---- interlude: per-head chunk-local softmax (m, Z); sc <- exp(s-m) ----
    {
        int h0 = w * 2;
        #pragma unroll
        for (int hh = 0; hh < 2; hh++) {
            int h = h0 + hh;
            float m = -1e30f;
            #pragma unroll
            for (int i = lane; i < SCHUNK; i += 32) m = fmaxf(m, sc[h][i]);
            #pragma unroll
            for (int o = 16; o; o >>= 1) m = fmaxf(m, __shfl_xor_sync(~0u, m, o));
            float z = 0.f;
            #pragma unroll
            for (int i = lane; i < SCHUNK; i += 32) {
                float p = __expf(sc[h][i] - m);
                sc[h][i] = p;
                z += p;
            }
            #pragma unroll
            for (int o = 16; o; o >>= 1) z += __shfl_xor_sync(~0u, z, o);
            if (lane == 0) {
                size_t mzb = ((size_t)(b * NCHUNK + ch) * HH + h) * 2;
                g_mz[mzb] = m;
                g_mz[mzb + 1] = z;
            }
        }
    }
    __syncthreads();

    // ---- phase 2: y_part = sum_s p[h][s] * x[s, :]. 96 threads per half-chunk,
    //      each owns 8 columns: {4u..4u+3} and {384+4u..384+4u+3} ----
    int half = t / 96, u = t - half * 96;
    int rem = SS - (s0 + half * 96);
    int slim = rem < 0 ? 0 : (rem > 96 ? 96 : rem);
    const float* xp = xb + (size_t)(s0 + half * 96) * CC;

    u64 acc2[HH][4];
    #pragma unroll
    for (int h = 0; h < HH; h++)
        #pragma unroll
        for (int k = 0; k < 4; k++) acc2[h][k] = 0ull;

    #pragma unroll 2
    for (int s = 0; s < slim; s++) {
        ulonglong2 xa = *(const ulonglong2*)(xp + (size_t)s * CC + 4 * u);
        ulonglong2 xc = *(const ulonglong2*)(xp + (size_t)s * CC + 384 + 4 * u);
        #pragma unroll
        for (int h = 0; h < HH; h++) {
            float p = sc[h][half * 96 + s];
            u64 pp = pk2(p, p);
            ffma2(acc2[h][0], pp, xa.x);
            ffma2(acc2[h][1], pp, xa.y);
            ffma2(acc2[h][2], pp, xc.x);
            ffma2(acc2[h][3], pp, xc.y);
        }
    }
    float* yp = g_ypart + ((size_t)(b * NCHUNK + ch) * 2 + half) * (HH * CC);
    #pragma unroll
    for (int h = 0; h < HH; h++) {
        float2 l0 = up2(acc2[h][0]), l1 = up2(acc2[h][1]);
        float2 l2 = up2(acc2[h][2]), l3 = up2(acc2[h][3]);
        *(float4*)(yp + h * CC + 4 * u)       = make_float4(l0.x, l0.y, l1.x, l1.y);
        *(float4*)(yp + h * CC + 384 + 4 * u) = make_float4(l2.x, l2.y, l3.x, l3.y);
    }
}

// ================= combine: global softmax weights + reduce ypart -> y =================
// block = (h, b), 128 threads.
__global__ __launch_bounds__(128) void k_combine() {
    int h = blockIdx.x, b = blockIdx.y, t = threadIdx.x;
    __shared__ float wgt[NCHUNK];

    if (t < 32) {
        float m = (t < NCHUNK) ? g_mz[((size_t)(b * NCHUNK + t) * HH + h) * 2] : -1e30f;
        float M = m;
        #pragma unroll
        for (int o = 16; o; o >>= 1) M = fmaxf(M, __shfl_xor_sync(~0u, M, o));
        float z = (t < NCHUNK) ? g_mz[((size_t)(b * NCHUNK + t) * HH + h) * 2 + 1] * __expf(m - M) : 0.f;
        float Z = z;
        #pragma unroll
        for (int o = 16; o; o >>= 1) Z += __shfl_xor_sync(~0u, Z, o);
        if (t < NCHUNK) wgt[t] = __expf(m - M) / Z;
    }
    __syncthreads();

    #pragma unroll
    for (int i = 0; i < 6; i++) {
        int c = t + 128 * i;
        float a = 0.f;
        for (int ch = 0; ch < NCHUNK; ch++) {
            size_t base = ((size_t)(b * NCHUNK + ch) * 2) * (HH * CC) + h * CC + c;
            a += wgt[ch] * (g_ypart[base] + g_ypart[base + HH * CC]);
        }
        g_y[(b * HH + h) * CC + c] = a;
    }
}

// ================= ctx + out: two tiny GEMVs per batch =================
__global__ __launch_bounds__(256) void k_ctxout(const float* __restrict__ Wv,
                                                const float* __restrict__ bv,
                                                const float* __restrict__ Wo,
                                                const float* __restrict__ bo,
                                                float* __restrict__ out) {
    int b = blockIdx.x, t = threadIdx.x;
    __shared__ float ys[HH * CC];   // 36 KB
    __shared__ float cso[CC];       // 3 KB
    for (int i = t; i < HH * CC; i += 256) ys[i] = g_y[b * HH * CC + i];
    __syncthreads();
    for (int o = t; o < CC; o += 256) {
        int h = o >> 6;
        float a = bv[o];
        const float* yrow = ys + h * CC;
        #pragma unroll 8
        for (int c = 0; c < CC; c++)
            a = fmaf(yrow[c], Wv[(size_t)c * CC + o], a);
        cso[o] = a;
    }
    __syncthreads();
    for (int cp = t; cp < CC; cp += 256) {
        float a = bo[cp];
        #pragma unroll 8
        for (int o = 0; o < CC; o++)
            a = fmaf(cso[o], Wo[(size_t)o * CC + cp], a);
        out[(size_t)b * CC + cp] = a;
    }
}

extern "C" void kernel_launch(void* const* d_in, const int* in_sizes, int n_in,
                              void* d_out, int out_size) {
    const float* x     = (const float*)d_in[0];
    const float* probe = (const float*)d_in[1];
    const float* Wq    = (const float*)d_in[2];
    const float* bq    = (const float*)d_in[3];
    const float* Wk    = (const float*)d_in[4];
    const float* bk    = (const float*)d_in[5];
    const float* Wv    = (const float*)d_in[6];
    const float* bv    = (const float*)d_in[7];
    const float* Wo    = (const float*)d_in[8];
    const float* bo    = (const float*)d_in[9];
    float* out = (float*)d_out;

    k_prep<<<HH, 256>>>(probe, Wq, bq, Wk, bk);
    k_fused<<<dim3(NCHUNK, BB), 192>>>(x);
    k_combine<<<dim3(HH, BB), 128>>>();
    k_ctxout<<<BB, 256>>>(Wv, bv, Wo, bo, out);
}

// round 3
// speedup vs baseline: 1.4648x; 1.4648x over previous
#include <cuda_runtime.h>

#define BB 32
#define SS 4096
#define CC 768
#define HH 12
#define DD 64
#define NCHUNK 43
#define SCHUNK 96

// ---- scratch (device globals; allocation is forbidden) ----
__device__ float g_wk[HH * CC];                                    // folded key weights
__device__ float g_sbias[HH];                                      // qh . bk
__device__ float g_z[BB * NCHUNK * HH];                            // per-chunk expsum
__device__ float g_ypart[(size_t)BB * NCHUNK * 2 * HH * CC];       // per (chunk,half) partial y
__device__ float g_y[BB * HH * CC];                                // combined, normalized y
__device__ float g_ctx[BB * CC];                                   // context (h,d flattened)

typedef unsigned long long u64;

__device__ __forceinline__ u64 pk2(float a, float b) {
    u64 r; asm("mov.b64 %0,{%1,%2};" : "=l"(r) : "f"(a), "f"(b)); return r;
}
__device__ __forceinline__ float2 up2(u64 v) {
    float2 r; asm("mov.b64 {%0,%1},%2;" : "=f"(r.x), "=f"(r.y) : "l"(v)); return r;
}
__device__ __forceinline__ void ffma2(u64& d, u64 a, u64 b) {
    asm("fma.rn.f32x2 %0,%1,%2,%0;" : "+l"(d) : "l"(a), "l"(b));
}
__device__ __forceinline__ u64 vadd2(u64 a, u64 b) {
    u64 r; asm("add.rn.f32x2 %0,%1,%2;" : "=l"(r) : "l"(a), "l"(b)); return r;
}

// ================= prep: qh then wk, one block per head =================
__global__ __launch_bounds__(256) void k_prep(const float* __restrict__ probe,
                                              const float* __restrict__ Wq,
                                              const float* __restrict__ bq,
                                              const float* __restrict__ Wk,
                                              const float* __restrict__ bk) {
    int h = blockIdx.x, t = threadIdx.x;
    __shared__ float red[4][DD];
    __shared__ float qs[DD];
    int d = t & 63, part = t >> 6;
    float a = 0.f;
    #pragma unroll 8
    for (int c = part; c < CC; c += 4)
        a = fmaf(probe[c], Wq[(size_t)c * CC + h * DD + d], a);
    red[part][d] = a;
    __syncthreads();
    if (t < DD)
        qs[t] = (red[0][t] + red[1][t] + red[2][t] + red[3][t] + bq[h * DD + t]) * 0.125f;
    __syncthreads();
    for (int c = t; c < CC; c += 256) {
        const float4* wr = (const float4*)(Wk + (size_t)c * CC + h * DD);
        float s = 0.f;
        #pragma unroll
        for (int j = 0; j < DD / 4; j++) {
            float4 wv = wr[j];
            const float4 qv = *(const float4*)(qs + 4 * j);
            s += wv.x * qv.x + wv.y * qv.y + wv.z * qv.z + wv.w * qv.w;
        }
        g_wk[h * CC + c] = s;
    }
    if (t == 0) {
        float s = 0.f;
        for (int d2 = 0; d2 < DD; d2++) s += bk[h * DD + d2] * qs[d2];
        g_sbias[h] = s;
    }
}

// ================= fused: scores -> exp (no max-sub) -> weighted accumulate =================
// block = (chunk, batch), 192 threads. SCHUNK=96 keeps the x tile L2-resident
// between phase 1 and phase 2.
__global__ __launch_bounds__(192) void k_fused(const float* __restrict__ x) {
    __shared__ float wks[HH * CC];          // 36 KB
    __shared__ float sc[HH][SCHUNK];        // 4.5 KB: exp(score)
    __shared__ float sbs[HH];

    int t = threadIdx.x, ch = blockIdx.x, b = blockIdx.y;
    int s0 = ch * SCHUNK;
    for (int i = t; i < HH * CC; i += 192) wks[i] = g_wk[i];
    if (t < HH) sbs[t] = g_sbias[t];
    __syncthreads();

    int lane = t & 31, w = t >> 5, g = lane >> 3, q = lane & 7;
    const float* xb = x + (size_t)b * SS * CC;

    // ---- phase 1: p = exp(score). quad layout, 4 rows per thread, 16 per warp ----
    {
        int lbase = w * 16 + g;                        // local row = lbase + 4k
        const ulonglong2* xr[4];
        #pragma unroll
        for (int k = 0; k < 4; k++) {
            int row = s0 + lbase + 4 * k;
            int rc = row < SS ? row : SS - 1;
            xr[k] = (const ulonglong2*)(xb + (size_t)rc * CC) + q;
        }
        const ulonglong2* wq = (const ulonglong2*)wks + q;

        u64 acc[HH][4];
        #pragma unroll
        for (int h = 0; h < HH; h++)
            #pragma unroll
            for (int k = 0; k < 4; k++) acc[h][k] = 0ull;

        #pragma unroll 4
        for (int j = 0; j < 24; j++) {
            ulonglong2 xv0 = xr[0][j * 8];
            ulonglong2 xv1 = xr[1][j * 8];
            ulonglong2 xv2 = xr[2][j * 8];
            ulonglong2 xv3 = xr[3][j * 8];
            const ulonglong2* wj = wq + j * 8;
            #pragma unroll
            for (int h = 0; h < HH; h++) {
                ulonglong2 wv = wj[h * (CC / 4)];
                ffma2(acc[h][0], xv0.x, wv.x); ffma2(acc[h][0], xv0.y, wv.y);
                ffma2(acc[h][1], xv1.x, wv.x); ffma2(acc[h][1], xv1.y, wv.y);
                ffma2(acc[h][2], xv2.x, wv.x); ffma2(acc[h][2], xv2.y, wv.y);
                ffma2(acc[h][3], xv3.x, wv.x); ffma2(acc[h][3], xv3.y, wv.y);
            }
        }
        #pragma unroll
        for (int h = 0; h < HH; h++) {
            #pragma unroll
            for (int k = 0; k < 4; k++) {
                u64 v = acc[h][k];
                v = vadd2(v, __shfl_xor_sync(0xffffffffu, v, 4));
                v = vadd2(v, __shfl_xor_sync(0xffffffffu, v, 2));
                v = vadd2(v, __shfl_xor_sync(0xffffffffu, v, 1));
                if (q == 0) {
                    int lr = lbase + 4 * k;
                    float2 f = up2(v);
                    sc[h][lr] = (s0 + lr < SS) ? __expf(f.x + f.y + sbs[h]) : 0.f;
                }
            }
        }
    }
    __syncthreads();

    // ---- interlude: z[h] = sum_s p  (cheap; no max pass needed) ----
    if (w < 6) {
        #pragma unroll
        for (int hh = 0; hh < 2; hh++) {
            int h = w * 2 + hh;
            float z = sc[h][lane] + sc[h][lane + 32] + sc[h][lane + 64];
            #pragma unroll
            for (int o = 16; o; o >>= 1) z += __shfl_xor_sync(~0u, z, o);
            if (lane == 0) g_z[(b * NCHUNK + ch) * HH + h] = z;
        }
    }

    // ---- phase 2: y_part = sum_s p[h][s] * x[s,:]. halves of 48 rows,
    //      96 threads/half, thread owns cols {4u..4u+3, 384+4u..384+4u+3} ----
    int half = t / 96, u = t - half * 96;
    int rem = SS - (s0 + half * 48);
    int slim = rem < 0 ? 0 : (rem > 48 ? 48 : rem);
    const float* xp = xb + (size_t)(s0 + half * 48) * CC + 4 * u;

    u64 acc2[HH][4];
    #pragma unroll
    for (int h = 0; h < HH; h++)
        #pragma unroll
        for (int k = 0; k < 4; k++) acc2[h][k] = 0ull;

    if (slim == 48) {
        for (int sb = 0; sb < 48; sb += 4) {
            ulonglong2 xa[4], xc[4];
            #pragma unroll
            for (int k = 0; k < 4; k++) {
                xa[k] = *(const ulonglong2*)(xp + (size_t)(sb + k) * CC);
                xc[k] = *(const ulonglong2*)(xp + (size_t)(sb + k) * CC + 384);
            }
            #pragma unroll
            for (int k = 0; k < 4; k++) {
                #pragma unroll
                for (int h = 0; h < HH; h++) {
                    float p = sc[h][half * 48 + sb + k];
                    u64 pp = pk2(p, p);
                    ffma2(acc2[h][0], pp, xa[k].x);
                    ffma2(acc2[h][1], pp, xa[k].y);
                    ffma2(acc2[h][2], pp, xc[k].x);
                    ffma2(acc2[h][3], pp, xc[k].y);
                }
            }
        }
    } else {
        for (int s = 0; s < slim; s++) {
            ulonglong2 xa = *(const ulonglong2*)(xp + (size_t)s * CC);
            ulonglong2 xc = *(const ulonglong2*)(xp + (size_t)s * CC + 384);
            #pragma unroll
            for (int h = 0; h < HH; h++) {
                float p = sc[h][half * 48 + s];
                u64 pp = pk2(p, p);
                ffma2(acc2[h][0], pp, xa.x);
                ffma2(acc2[h][1], pp, xa.y);
                ffma2(acc2[h][2], pp, xc.x);
                ffma2(acc2[h][3], pp, xc.y);
            }
        }
    }
    float* yp = g_ypart + ((size_t)(b * NCHUNK + ch) * 2 + half) * (HH * CC);
    #pragma unroll
    for (int h = 0; h < HH; h++) {
        float2 l0 = up2(acc2[h][0]), l1 = up2(acc2[h][1]);
        float2 l2 = up2(acc2[h][2]), l3 = up2(acc2[h][3]);
        *(float4*)(yp + h * CC + 4 * u)       = make_float4(l0.x, l0.y, l1.x, l1.y);
        *(float4*)(yp + h * CC + 384 + 4 * u) = make_float4(l2.x, l2.y, l3.x, l3.y);
    }
}

// ================= combine: y = (sum_ch ypart) / (sum_ch z) =================
// block = (h, b), 256 threads, 3 columns each.
__global__ __launch_bounds__(256) void k_combine() {
    int h = blockIdx.x, b = blockIdx.y, t = threadIdx.x;
    __shared__ float invZ_s;
    if (t < 64) {
        float z = 0.f;
        if (t < NCHUNK) z = g_z[(b * NCHUNK + t) * HH + h];
        #pragma unroll
        for (int o = 16; o; o >>= 1) z += __shfl_xor_sync(~0u, z, o);
        if (t == 0) {
            float z2; asm("ld.shared.f32 %0, [%1];" : "=f"(z2) : "r"(0)); // dummy
            invZ_s = 0.f;  // init; real value below
        }
    }
    __syncthreads();
    // redo reduction cleanly with two warps worth folded by warp 0
    if (t < 32) {
        float z = 0.f;
        for (int c2 = t; c2 < NCHUNK; c2 += 32) z += g_z[(b * NCHUNK + c2) * HH + h];
        #pragma unroll
        for (int o = 16; o; o >>= 1) z += __shfl_xor_sync(~0u, z, o);
        if (t == 0) invZ_s = 1.f / z;
    }
    __syncthreads();
    float invZ = invZ_s;

    #pragma unroll
    for (int i = 0; i < 3; i++) {
        int c = t + 256 * i;
        float a = 0.f;
        const float* base = g_ypart + (size_t)b * NCHUNK * 2 * HH * CC + h * CC + c;
        #pragma unroll 4
        for (int ch = 0; ch < NCHUNK; ch++) {
            a += base[(size_t)ch * 2 * HH * CC];
            a += base[(size_t)(ch * 2 + 1) * HH * CC];
        }
        g_y[(b * HH + h) * CC + c] = a * invZ;
    }
}

// ================= ctx: ctx[b,h,d] = sum_c y[b,h,c] * Wv[c,h,d] + bv =================
// block = (b, h), 256 threads: 4 c-partitions x 64 d.
__global__ __launch_bounds__(256) void k_ctx(const float* __restrict__ Wv,
                                             const float* __restrict__ bv) {
    int b = blockIdx.x, h = blockIdx.y, t = threadIdx.x;
    __shared__ float ys[CC];
    __shared__ float red[4][DD];
    for (int i = t; i < CC; i += 256) ys[i] = g_y[(b * HH + h) * CC + i];
    __syncthreads();
    int d = t & 63, part = t >> 6;
    const float* wp = Wv + h * DD + d;
    float a = 0.f;
    #pragma unroll 8
    for (int c = part; c < CC; c += 4)
        a = fmaf(ys[c], wp[(size_t)c * CC], a);
    red[part][d] = a;
    __syncthreads();
    if (t < DD)
        g_ctx[b * CC + h * DD + t] =
            red[0][t] + red[1][t] + red[2][t] + red[3][t] + bv[h * DD + t];
}

// ================= out: out[b,c'] = sum_o ctx[b,o] * Wo[o,c'] + bo =================
// block = (b, part), 192 threads, 1 column each, 4 accumulators.
__global__ __launch_bounds__(192) void k_out(const float* __restrict__ Wo,
                                             const float* __restrict__ bo,
                                             float* __restrict__ out) {
    int b = blockIdx.x, part = blockIdx.y, t = threadIdx.x;
    __shared__ float cs[CC];
    for (int i = t; i < CC; i += 192) cs[i] = g_ctx[b * CC + i];
    __syncthreads();
    int cp = part * 192 + t;
    const float* wp = Wo + cp;
    float a0 = 0.f, a1 = 0.f, a2 = 0.f, a3 = 0.f;
    #pragma unroll 8
    for (int o = 0; o < CC; o += 4) {
        a0 = fmaf(cs[o],     wp[(size_t)o * CC],       a0);
        a1 = fmaf(cs[o + 1], wp[(size_t)(o + 1) * CC], a1);
        a2 = fmaf(cs[o + 2], wp[(size_t)(o + 2) * CC], a2);
        a3 = fmaf(cs[o + 3], wp[(size_t)(o + 3) * CC], a3);
    }
    out[(size_t)b * CC + cp] = (a0 + a1) + (a2 + a3) + bo[cp];
}

extern "C" void kernel_launch(void* const* d_in, const int* in_sizes, int n_in,
                              void* d_out, int out_size) {
    const float* x     = (const float*)d_in[0];
    const float* probe = (const float*)d_in[1];
    const float* Wq    = (const float*)d_in[2];
    const float* bq    = (const float*)d_in[3];
    const float* Wk    = (const float*)d_in[4];
    const float* bk    = (const float*)d_in[5];
    const float* Wv    = (const float*)d_in[6];
    const float* bv    = (const float*)d_in[7];
    const float* Wo    = (const float*)d_in[8];
    const float* bo    = (const float*)d_in[9];
    float* out = (float*)d_out;

    k_prep<<<HH, 256>>>(probe, Wq, bq, Wk, bk);
    k_fused<<<dim3(NCHUNK, BB), 192>>>(x);
    k_combine<<<dim3(HH, BB), 256>>>();
    k_ctx<<<dim3(BB, HH), 256>>>(Wv, bv);
    k_out<<<dim3(BB, 4), 192>>>(Wo, bo, out);
}

// round 4
// speedup vs baseline: 1.5724x; 1.0734x over previous
#include <cuda_runtime.h>

#define BB 32
#define SS 4096
#define CC 768
#define HH 12
#define DD 64
#define NCHUNK 43
#define SCHUNK 96

// ---- scratch (device globals; allocation is forbidden) ----
__device__ float g_qh[HH * DD];                               // scaled probe query
__device__ float g_wk[HH * CC];                               // folded key weights
__device__ float g_sbias[HH];                                 // qh . bk
__device__ float g_z[BB * NCHUNK * HH];                       // per-chunk expsum
__device__ float g_ypart[(size_t)BB * NCHUNK * HH * CC];      // per-chunk partial y (50.7 MB)
__device__ float g_ctx[BB * CC];                              // context (h,d flattened)

typedef unsigned long long u64;

__device__ __forceinline__ u64 pk2(float a, float b) {
    u64 r; asm("mov.b64 %0,{%1,%2};" : "=l"(r) : "f"(a), "f"(b)); return r;
}
__device__ __forceinline__ float2 up2(u64 v) {
    float2 r; asm("mov.b64 {%0,%1},%2;" : "=f"(r.x), "=f"(r.y) : "l"(v)); return r;
}
__device__ __forceinline__ void ffma2(u64& d, u64 a, u64 b) {
    asm("fma.rn.f32x2 %0,%1,%2,%0;" : "+l"(d) : "l"(a), "l"(b));
}
__device__ __forceinline__ u64 vadd2(u64 a, u64 b) {
    u64 r; asm("add.rn.f32x2 %0,%1,%2;" : "=l"(r) : "l"(a), "l"(b)); return r;
}

// ================= prep 1: qh = (probe @ Wq + bq)/8 =================
__global__ __launch_bounds__(256) void k_prep_qh(const float* __restrict__ probe,
                                                 const float* __restrict__ Wq,
                                                 const float* __restrict__ bq) {
    int h = blockIdx.x, t = threadIdx.x;
    __shared__ float red[4][DD];
    int d = t & 63, part = t >> 6;
    float a = 0.f;
    #pragma unroll 8
    for (int c = part; c < CC; c += 4)
        a = fmaf(probe[c], Wq[(size_t)c * CC + h * DD + d], a);
    red[part][d] = a;
    __syncthreads();
    if (t < DD)
        g_qh[h * DD + t] = (red[0][t] + red[1][t] + red[2][t] + red[3][t] + bq[h * DD + t]) * 0.125f;
}

// ================= prep 2: wk[h,c] = sum_d Wk[c,h,d]*qh[h,d] =================
__global__ __launch_bounds__(256) void k_prep_wk(const float* __restrict__ Wk) {
    int h = blockIdx.x, t = threadIdx.x;
    __shared__ float qs[DD];
    if (t < DD) qs[t] = g_qh[h * DD + t];
    __syncthreads();
    for (int c = t; c < CC; c += 256) {
        const float4* wr = (const float4*)(Wk + (size_t)c * CC + h * DD);
        float s = 0.f;
        #pragma unroll
        for (int j = 0; j < DD / 4; j++) {
            float4 wv = wr[j];
            const float4 qv = *(const float4*)(qs + 4 * j);
            s += wv.x * qv.x + wv.y * qv.y + wv.z * qv.z + wv.w * qv.w;
        }
        g_wk[h * CC + c] = s;
    }
}

// ================= prep 3: sbias[h] = qh[h,:].bk[h,:] =================
__global__ __launch_bounds__(384) void k_prep_sb(const float* __restrict__ bk) {
    int t = threadIdx.x, h = t >> 5, lane = t & 31;
    float a = g_qh[h * DD + lane] * bk[h * DD + lane]
            + g_qh[h * DD + 32 + lane] * bk[h * DD + 32 + lane];
    #pragma unroll
    for (int o = 16; o; o >>= 1) a += __shfl_xor_sync(~0u, a, o);
    if (lane == 0) g_sbias[h] = a;
}

// ================= fused: scores -> exp -> weighted accumulate (launch #4) ===========
__global__ __launch_bounds__(192) void k_fused(const float* __restrict__ x) {
    __shared__ float uS[HH * CC];           // wks (phase 1) / y stage (phase 2) — 36 KB
    __shared__ float sc[HH][SCHUNK];        // exp(score), 4.5 KB
    __shared__ float sbs[HH];

    int t = threadIdx.x, ch = blockIdx.x, b = blockIdx.y;
    int s0 = ch * SCHUNK;
    for (int i = t; i < HH * CC; i += 192) uS[i] = g_wk[i];
    if (t < HH) sbs[t] = g_sbias[t];
    __syncthreads();

    int lane = t & 31, w = t >> 5, g = lane >> 3, q = lane & 7;
    const float* xb = x + (size_t)b * SS * CC;

    // ---- phase 1: p = exp(score). quad layout, 4 rows/thread, 16 rows/warp ----
    {
        int lbase = w * 16 + g;
        const ulonglong2* xr[4];
        #pragma unroll
        for (int k = 0; k < 4; k++) {
            int row = s0 + lbase + 4 * k;
            int rc = row < SS ? row : SS - 1;
            xr[k] = (const ulonglong2*)(xb + (size_t)rc * CC) + q;
        }
        const ulonglong2* wq = (const ulonglong2*)uS + q;

        u64 acc[HH][4];
        #pragma unroll
        for (int h = 0; h < HH; h++)
            #pragma unroll
            for (int k = 0; k < 4; k++) acc[h][k] = 0ull;

        #pragma unroll 4
        for (int j = 0; j < 24; j++) {
            ulonglong2 xv0 = xr[0][j * 8];
            ulonglong2 xv1 = xr[1][j * 8];
            ulonglong2 xv2 = xr[2][j * 8];
            ulonglong2 xv3 = xr[3][j * 8];
            const ulonglong2* wj = wq + j * 8;
            #pragma unroll
            for (int h = 0; h < HH; h++) {
                ulonglong2 wv = wj[h * (CC / 4)];
                ffma2(acc[h][0], xv0.x, wv.x); ffma2(acc[h][0], xv0.y, wv.y);
                ffma2(acc[h][1], xv1.x, wv.x); ffma2(acc[h][1], xv1.y, wv.y);
                ffma2(acc[h][2], xv2.x, wv.x); ffma2(acc[h][2], xv2.y, wv.y);
                ffma2(acc[h][3], xv3.x, wv.x); ffma2(acc[h][3], xv3.y, wv.y);
            }
        }
        #pragma unroll
        for (int h = 0; h < HH; h++) {
            #pragma unroll
            for (int k = 0; k < 4; k++) {
                u64 v = acc[h][k];
                v = vadd2(v, __shfl_xor_sync(0xffffffffu, v, 4));
                v = vadd2(v, __shfl_xor_sync(0xffffffffu, v, 2));
                v = vadd2(v, __shfl_xor_sync(0xffffffffu, v, 1));
                if (q == 0) {
                    int lr = lbase + 4 * k;
                    float2 f = up2(v);
                    sc[h][lr] = (s0 + lr < SS) ? __expf(f.x + f.y + sbs[h]) : 0.f;
                }
            }
        }
    }
    __syncthreads();   // sc visible to everyone; also last read of uS as wks is done

    // ---- interlude: z[h] = sum_s p ----
    if (w < 6) {
        #pragma unroll
        for (int hh = 0; hh < 2; hh++) {
            int h = w * 2 + hh;
            float z = sc[h][lane] + sc[h][lane + 32] + sc[h][lane + 64];
            #pragma unroll
            for (int o = 16; o; o >>= 1) z += __shfl_xor_sync(~0u, z, o);
            if (lane == 0) g_z[(b * NCHUNK + ch) * HH + h] = z;
        }
    }

    // ---- phase 2: 48-row halves; 96 threads/half own cols {4u..4u+3, 384+4u..} ----
    int half = t / 96, u = t - half * 96;
    int rem = SS - (s0 + half * 48);
    int slim = rem < 0 ? 0 : (rem > 48 ? 48 : rem);
    const float* xp = xb + (size_t)(s0 + half * 48) * CC + 4 * u;

    u64 acc2[HH][4];
    #pragma unroll
    for (int h = 0; h < HH; h++)
        #pragma unroll
        for (int k = 0; k < 4; k++) acc2[h][k] = 0ull;

    if (slim == 48) {
        for (int sb = 0; sb < 48; sb += 4) {
            ulonglong2 xa[4], xc[4];
            #pragma unroll
            for (int k = 0; k < 4; k++) {
                xa[k] = *(const ulonglong2*)(xp + (size_t)(sb + k) * CC);
                xc[k] = *(const ulonglong2*)(xp + (size_t)(sb + k) * CC + 384);
            }
            #pragma unroll
            for (int k = 0; k < 4; k++) {
                #pragma unroll
                for (int h = 0; h < HH; h++) {
                    float p = sc[h][half * 48 + sb + k];
                    u64 pp = pk2(p, p);
                    ffma2(acc2[h][0], pp, xa[k].x);
                    ffma2(acc2[h][1], pp, xa[k].y);
                    ffma2(acc2[h][2], pp, xc[k].x);
                    ffma2(acc2[h][3], pp, xc[k].y);
                }
            }
        }
    } else {
        for (int s = 0; s < slim; s++) {
            ulonglong2 xa = *(const ulonglong2*)(xp + (size_t)s * CC);
            ulonglong2 xc = *(const ulonglong2*)(xp + (size_t)s * CC + 384);
            #pragma unroll
            for (int h = 0; h < HH; h++) {
                float p = sc[h][half * 48 + s];
                u64 pp = pk2(p, p);
                ffma2(acc2[h][0], pp, xa.x);
                ffma2(acc2[h][1], pp, xa.y);
                ffma2(acc2[h][2], pp, xc.x);
                ffma2(acc2[h][3], pp, xc.y);
            }
        }
    }

    // half 1 stages into smem (uS reused; wks no longer needed)
    __syncthreads();
    if (half == 1) {
        #pragma unroll
        for (int h = 0; h < HH; h++) {
            float2 l0 = up2(acc2[h][0]), l1 = up2(acc2[h][1]);
            float2 l2 = up2(acc2[h][2]), l3 = up2(acc2[h][3]);
            *(float4*)(uS + h * CC + 4 * u)       = make_float4(l0.x, l0.y, l1.x, l1.y);
            *(float4*)(uS + h * CC + 384 + 4 * u) = make_float4(l2.x, l2.y, l3.x, l3.y);
        }
    }
    __syncthreads();
    if (half == 0) {
        float* yp = g_ypart + ((size_t)(b * NCHUNK + ch)) * (HH * CC);
        #pragma unroll
        for (int h = 0; h < HH; h++) {
            float2 l0 = up2(acc2[h][0]), l1 = up2(acc2[h][1]);
            float2 l2 = up2(acc2[h][2]), l3 = up2(acc2[h][3]);
            float4 s0v = *(const float4*)(uS + h * CC + 4 * u);
            float4 s1v = *(const float4*)(uS + h * CC + 384 + 4 * u);
            *(float4*)(yp + h * CC + 4 * u) =
                make_float4(l0.x + s0v.x, l0.y + s0v.y, l1.x + s0v.z, l1.y + s0v.w);
            *(float4*)(yp + h * CC + 384 + 4 * u) =
                make_float4(l2.x + s1v.x, l2.y + s1v.y, l3.x + s1v.z, l3.y + s1v.w);
        }
    }
}

// ================= combine + ctx: y = sum(ypart)/Z, ctx = y @ Wv + bv =================
// block = (b, h), 256 threads.
__global__ __launch_bounds__(256) void k_combctx(const float* __restrict__ Wv,
                                                 const float* __restrict__ bv) {
    int b = blockIdx.x, h = blockIdx.y, t = threadIdx.x;
    __shared__ float ys[CC];
    __shared__ float red[4][DD];
    __shared__ float invZ_s;

    if (t < 32) {
        float z = 0.f;
        for (int c2 = t; c2 < NCHUNK; c2 += 32) z += g_z[(b * NCHUNK + c2) * HH + h];
        #pragma unroll
        for (int o = 16; o; o >>= 1) z += __shfl_xor_sync(~0u, z, o);
        if (t == 0) invZ_s = 1.f / z;
    }
    __syncthreads();
    float invZ = invZ_s;

    #pragma unroll
    for (int i = 0; i < 3; i++) {
        int c = t + 256 * i;
        const float* base = g_ypart + (size_t)b * NCHUNK * HH * CC + h * CC + c;
        float a0 = 0.f, a1 = 0.f, a2 = 0.f, a3 = 0.f;
        #pragma unroll 4
        for (int ch = 0; ch < NCHUNK - 3; ch += 4) {
            a0 += base[(size_t)ch * HH * CC];
            a1 += base[(size_t)(ch + 1) * HH * CC];
            a2 += base[(size_t)(ch + 2) * HH * CC];
            a3 += base[(size_t)(ch + 3) * HH * CC];
        }
        for (int ch = NCHUNK & ~3; ch < NCHUNK; ch++)
            a0 += base[(size_t)ch * HH * CC];
        ys[c] = ((a0 + a1) + (a2 + a3)) * invZ;
    }
    __syncthreads();

    int d = t & 63, part = t >> 6;
    const float* wp = Wv + h * DD + d;
    float a0 = 0.f, a1 = 0.f;
    #pragma unroll 8
    for (int c = part; c < CC; c += 8) {
        a0 = fmaf(ys[c],     wp[(size_t)c * CC],       a0);
        a1 = fmaf(ys[c + 4], wp[(size_t)(c + 4) * CC], a1);
    }
    red[part][d] = a0 + a1;
    __syncthreads();
    if (t < DD)
        g_ctx[b * CC + h * DD + t] =
            red[0][t] + red[1][t] + red[2][t] + red[3][t] + bv[h * DD + t];
}

// ================= out: out[b,c'] = ctx[b,:] @ Wo + bo =================
__global__ __launch_bounds__(192) void k_out(const float* __restrict__ Wo,
                                             const float* __restrict__ bo,
                                             float* __restrict__ out) {
    int b = blockIdx.x, part = blockIdx.y, t = threadIdx.x;
    __shared__ float cs[CC];
    for (int i = t; i < CC; i += 192) cs[i] = g_ctx[b * CC + i];
    __syncthreads();
    int cp = part * 192 + t;
    const float* wp = Wo + cp;
    float a0 = 0.f, a1 = 0.f, a2 = 0.f, a3 = 0.f;
    #pragma unroll 8
    for (int o = 0; o < CC; o += 4) {
        a0 = fmaf(cs[o],     wp[(size_t)o * CC],       a0);
        a1 = fmaf(cs[o + 1], wp[(size_t)(o + 1) * CC], a1);
        a2 = fmaf(cs[o + 2], wp[(size_t)(o + 2) * CC], a2);
        a3 = fmaf(cs[o + 3], wp[(size_t)(o + 3) * CC], a3);
    }
    out[(size_t)b * CC + cp] = (a0 + a1) + (a2 + a3) + bo[cp];
}

extern "C" void kernel_launch(void* const* d_in, const int* in_sizes, int n_in,
                              void* d_out, int out_size) {
    const float* x     = (const float*)d_in[0];
    const float* probe = (const float*)d_in[1];
    const float* Wq    = (const float*)d_in[2];
    const float* bq    = (const float*)d_in[3];
    const float* Wk    = (const float*)d_in[4];
    const float* bk    = (const float*)d_in[5];
    const float* Wv    = (const float*)d_in[6];
    const float* bv    = (const float*)d_in[7];
    const float* Wo    = (const float*)d_in[8];
    const float* bo    = (const float*)d_in[9];
    float* out = (float*)d_out;

    k_prep_qh<<<HH, 256>>>(probe, Wq, bq);          // #1
    k_prep_wk<<<HH, 256>>>(Wk);                     // #2
    k_prep_sb<<<1, 384>>>(bk);                      // #3
    k_fused<<<dim3(NCHUNK, BB), 192>>>(x);          // #4  <- profiled
    k_combctx<<<dim3(BB, HH), 256>>>(Wv, bv);       // #5
    k_out<<<dim3(BB, 4), 192>>>(Wo, bo, out);       // #6
}

// round 5
// speedup vs baseline: 1.7733x; 1.1278x over previous
#include <cuda_runtime.h>

#define BB 32
#define SS 4096
#define CC 768
#define HH 12
#define DD 64
#define NCHUNK 43
#define SCHUNK 96

// ---- scratch (device globals; allocation is forbidden) ----
__device__ float g_qh[HH * DD];                               // scaled probe query
__device__ float g_wk[HH * CC];                               // folded key weights
__device__ float g_sbias[HH];                                 // qh . bk
__device__ float g_z[BB * NCHUNK * HH];                       // per-chunk expsum
__device__ float g_ypart[(size_t)BB * NCHUNK * HH * CC];      // per-chunk partial y
__device__ float g_ctx[BB * CC];                              // context (h,d flattened)

typedef unsigned long long u64;

__device__ __forceinline__ u64 pk2(float a, float b) {
    u64 r; asm("mov.b64 %0,{%1,%2};" : "=l"(r) : "f"(a), "f"(b)); return r;
}
__device__ __forceinline__ float2 up2(u64 v) {
    float2 r; asm("mov.b64 {%0,%1},%2;" : "=f"(r.x), "=f"(r.y) : "l"(v)); return r;
}
__device__ __forceinline__ void ffma2(u64& d, u64 a, u64 b) {
    asm("fma.rn.f32x2 %0,%1,%2,%0;" : "+l"(d) : "l"(a), "l"(b));
}
__device__ __forceinline__ u64 vadd2(u64 a, u64 b) {
    u64 r; asm("add.rn.f32x2 %0,%1,%2;" : "=l"(r) : "l"(a), "l"(b)); return r;
}

// ================= prep 1: qh = (probe @ Wq + bq)/8 =================
__global__ __launch_bounds__(256) void k_prep_qh(const float* __restrict__ probe,
                                                 const float* __restrict__ Wq,
                                                 const float* __restrict__ bq) {
    int h = blockIdx.x, t = threadIdx.x;
    __shared__ float red[4][DD];
    int d = t & 63, part = t >> 6;
    float a = 0.f;
    #pragma unroll 8
    for (int c = part; c < CC; c += 4)
        a = fmaf(probe[c], Wq[(size_t)c * CC + h * DD + d], a);
    red[part][d] = a;
    __syncthreads();
    if (t < DD)
        g_qh[h * DD + t] = (red[0][t] + red[1][t] + red[2][t] + red[3][t] + bq[h * DD + t]) * 0.125f;
}

// ================= prep 2: wk[h,c] = sum_d Wk[c,h,d]*qh[h,d] =================
__global__ __launch_bounds__(256) void k_prep_wk(const float* __restrict__ Wk) {
    int h = blockIdx.x, t = threadIdx.x;
    __shared__ float qs[DD];
    if (t < DD) qs[t] = g_qh[h * DD + t];
    __syncthreads();
    for (int c = t; c < CC; c += 256) {
        const float4* wr = (const float4*)(Wk + (size_t)c * CC + h * DD);
        float s = 0.f;
        #pragma unroll
        for (int j = 0; j < DD / 4; j++) {
            float4 wv = wr[j];
            const float4 qv = *(const float4*)(qs + 4 * j);
            s += wv.x * qv.x + wv.y * qv.y + wv.z * qv.z + wv.w * qv.w;
        }
        g_wk[h * CC + c] = s;
    }
}

// ================= prep 3: sbias[h] = qh[h,:].bk[h,:] =================
__global__ __launch_bounds__(384) void k_prep_sb(const float* __restrict__ bk) {
    int t = threadIdx.x, h = t >> 5, lane = t & 31;
    float a = g_qh[h * DD + lane] * bk[h * DD + lane]
            + g_qh[h * DD + 32 + lane] * bk[h * DD + 32 + lane];
    #pragma unroll
    for (int o = 16; o; o >>= 1) a += __shfl_xor_sync(~0u, a, o);
    if (lane == 0) g_sbias[h] = a;
}

// ================= fused: scores -> exp -> weighted accumulate (launch #4) ===========
// 384 threads, 2 blocks/SM (24 warps). Phase 1: warp pairs split heads 6+6,
// 4 rows/thread (acc[6][4]=48 regs). Phase 2: 4 cols/thread, 48-row halves
// (acc2[12][2]=48 regs). exp weights stored pre-duplicated (u64) in smem.
__global__ __launch_bounds__(384, 2) void k_fused(const float* __restrict__ x) {
    __shared__ __align__(16) float uS[HH * CC];      // wk (phase 1) / y stage (phase 2)
    __shared__ __align__(16) u64 scd[HH][SCHUNK];    // exp(score) duplicated, 9 KB
    __shared__ float zsh[HH];
    __shared__ float sbs[HH];

    int t = threadIdx.x, ch = blockIdx.x, b = blockIdx.y;
    int s0 = ch * SCHUNK;
    for (int i = t; i < HH * CC; i += 384) uS[i] = g_wk[i];
    if (t < HH) { sbs[t] = g_sbias[t]; zsh[t] = 0.f; }
    __syncthreads();

    int lane = t & 31, w = t >> 5, g = lane >> 3, q = lane & 7;
    const float* xb = x + (size_t)b * SS * CC;

    // ---- phase 1 ----
    {
        int p = w >> 1, h0 = (w & 1) * 6;
        int lbase = p * 16 + g;                        // local row = lbase + 4k
        const ulonglong2* xr[4];
        #pragma unroll
        for (int k = 0; k < 4; k++) {
            int row = s0 + lbase + 4 * k;
            int rc = row < SS ? row : SS - 1;
            xr[k] = (const ulonglong2*)(xb + (size_t)rc * CC) + q;
        }
        const ulonglong2* wq = (const ulonglong2*)uS + h0 * (CC / 4) + q;

        u64 acc[6][4];
        #pragma unroll
        for (int i = 0; i < 6; i++)
            #pragma unroll
            for (int k = 0; k < 4; k++) acc[i][k] = 0ull;

        #pragma unroll 4
        for (int j = 0; j < 24; j++) {
            ulonglong2 xv0 = xr[0][j * 8];
            ulonglong2 xv1 = xr[1][j * 8];
            ulonglong2 xv2 = xr[2][j * 8];
            ulonglong2 xv3 = xr[3][j * 8];
            #pragma unroll
            for (int i = 0; i < 6; i++) {
                ulonglong2 wv = wq[i * (CC / 4) + j * 8];
                ffma2(acc[i][0], xv0.x, wv.x); ffma2(acc[i][0], xv0.y, wv.y);
                ffma2(acc[i][1], xv1.x, wv.x); ffma2(acc[i][1], xv1.y, wv.y);
                ffma2(acc[i][2], xv2.x, wv.x); ffma2(acc[i][2], xv2.y, wv.y);
                ffma2(acc[i][3], xv3.x, wv.x); ffma2(acc[i][3], xv3.y, wv.y);
            }
        }
        #pragma unroll
        for (int i = 0; i < 6; i++) {
            float zt = 0.f;
            #pragma unroll
            for (int k = 0; k < 4; k++) {
                u64 v = acc[i][k];
                v = vadd2(v, __shfl_xor_sync(0xffffffffu, v, 4));
                v = vadd2(v, __shfl_xor_sync(0xffffffffu, v, 2));
                v = vadd2(v, __shfl_xor_sync(0xffffffffu, v, 1));
                if (q == 0) {
                    int lr = lbase + 4 * k;
                    float2 f = up2(v);
                    float e = (s0 + lr < SS) ? __expf(f.x + f.y + sbs[h0 + i]) : 0.f;
                    scd[h0 + i][lr] = pk2(e, e);
                    zt += e;
                }
            }
            float zq = (q == 0) ? zt : 0.f;
            zq += __shfl_xor_sync(0xffffffffu, zq, 8);
            zq += __shfl_xor_sync(0xffffffffu, zq, 16);
            if (lane == 0) atomicAdd(&zsh[h0 + i], zq);
        }
    }
    __syncthreads();
    if (t < HH) g_z[(b * NCHUNK + ch) * HH + t] = zsh[t];

    // ---- phase 2: y_part = sum_s p[h][s] * x[s,:] ----
    int half = t / 192, u = t - half * 192;            // cols 4u..4u+3
    int bs = half * 48;
    int rem = SS - (s0 + bs);
    int slim = rem < 0 ? 0 : (rem > 48 ? 48 : rem);    // always even
    const float* xp = xb + (size_t)(s0 + bs) * CC + 4 * u;

    u64 acc2[HH][2];
    #pragma unroll
    for (int h = 0; h < HH; h++) { acc2[h][0] = 0ull; acc2[h][1] = 0ull; }

    #pragma unroll 2
    for (int s2 = 0; s2 < slim / 2; s2++) {
        ulonglong2 x0 = *(const ulonglong2*)(xp + (size_t)(2 * s2) * CC);
        ulonglong2 x1 = *(const ulonglong2*)(xp + (size_t)(2 * s2 + 1) * CC);
        #pragma unroll
        for (int h = 0; h < HH; h++) {
            ulonglong2 pv = *(const ulonglong2*)&scd[h][bs + 2 * s2];
            ffma2(acc2[h][0], pv.x, x0.x); ffma2(acc2[h][1], pv.x, x0.y);
            ffma2(acc2[h][0], pv.y, x1.x); ffma2(acc2[h][1], pv.y, x1.y);
        }
    }

    // half 1 stages into uS (wk no longer needed); half 0 merges and writes
    __syncthreads();
    if (half == 1) {
        #pragma unroll
        for (int h = 0; h < HH; h++) {
            float2 l0 = up2(acc2[h][0]), l1 = up2(acc2[h][1]);
            *(float4*)(uS + h * CC + 4 * u) = make_float4(l0.x, l0.y, l1.x, l1.y);
        }
    }
    __syncthreads();
    if (half == 0) {
        float* yp = g_ypart + ((size_t)(b * NCHUNK + ch)) * (HH * CC);
        #pragma unroll
        for (int h = 0; h < HH; h++) {
            float2 l0 = up2(acc2[h][0]), l1 = up2(acc2[h][1]);
            float4 sv = *(const float4*)(uS + h * CC + 4 * u);
            *(float4*)(yp + h * CC + 4 * u) =
                make_float4(l0.x + sv.x, l0.y + sv.y, l1.x + sv.z, l1.y + sv.w);
        }
    }
}

// ================= combine + ctx: y = sum(ypart)/Z, ctx = y @ Wv + bv =================
__global__ __launch_bounds__(256) void k_combctx(const float* __restrict__ Wv,
                                                 const float* __restrict__ bv) {
    int b = blockIdx.x, h = blockIdx.y, t = threadIdx.x;
    __shared__ float ys[CC];
    __shared__ float red[4][DD];
    __shared__ float invZ_s;

    if (t < 32) {
        float z = 0.f;
        for (int c2 = t; c2 < NCHUNK; c2 += 32) z += g_z[(b * NCHUNK + c2) * HH + h];
        #pragma unroll
        for (int o = 16; o; o >>= 1) z += __shfl_xor_sync(~0u, z, o);
        if (t == 0) invZ_s = 1.f / z;
    }
    __syncthreads();
    float invZ = invZ_s;

    #pragma unroll
    for (int i = 0; i < 3; i++) {
        int c = t + 256 * i;
        const float* base = g_ypart + (size_t)b * NCHUNK * HH * CC + h * CC + c;
        float a0 = 0.f, a1 = 0.f, a2 = 0.f, a3 = 0.f;
        #pragma unroll 4
        for (int chn = 0; chn < NCHUNK - 3; chn += 4) {
            a0 += base[(size_t)chn * HH * CC];
            a1 += base[(size_t)(chn + 1) * HH * CC];
            a2 += base[(size_t)(chn + 2) * HH * CC];
            a3 += base[(size_t)(chn + 3) * HH * CC];
        }
        for (int chn = NCHUNK & ~3; chn < NCHUNK; chn++)
            a0 += base[(size_t)chn * HH * CC];
        ys[c] = ((a0 + a1) + (a2 + a3)) * invZ;
    }
    __syncthreads();

    int d = t & 63, part = t >> 6;
    const float* wp = Wv + h * DD + d;
    float a0 = 0.f, a1 = 0.f;
    #pragma unroll 8
    for (int c = part; c < CC; c += 8) {
        a0 = fmaf(ys[c],     wp[(size_t)c * CC],       a0);
        a1 = fmaf(ys[c + 4], wp[(size_t)(c + 4) * CC], a1);
    }
    red[part][d] = a0 + a1;
    __syncthreads();
    if (t < DD)
        g_ctx[b * CC + h * DD + t] =
            red[0][t] + red[1][t] + red[2][t] + red[3][t] + bv[h * DD + t];
}

// ================= out: out[b,c'] = ctx[b,:] @ Wo + bo =================
__global__ __launch_bounds__(192) void k_out(const float* __restrict__ Wo,
                                             const float* __restrict__ bo,
                                             float* __restrict__ out) {
    int b = blockIdx.x, part = blockIdx.y, t = threadIdx.x;
    __shared__ float cs[CC];
    for (int i = t; i < CC; i += 192) cs[i] = g_ctx[b * CC + i];
    __syncthreads();
    int cp = part * 192 + t;
    const float* wp = Wo + cp;
    float a0 = 0.f, a1 = 0.f, a2 = 0.f, a3 = 0.f;
    #pragma unroll 8
    for (int o = 0; o < CC; o += 4) {
        a0 = fmaf(cs[o],     wp[(size_t)o * CC],       a0);
        a1 = fmaf(cs[o + 1], wp[(size_t)(o + 1) * CC], a1);
        a2 = fmaf(cs[o + 2], wp[(size_t)(o + 2) * CC], a2);
        a3 = fmaf(cs[o + 3], wp[(size_t)(o + 3) * CC], a3);
    }
    out[(size_t)b * CC + cp] = (a0 + a1) + (a2 + a3) + bo[cp];
}

extern "C" void kernel_launch(void* const* d_in, const int* in_sizes, int n_in,
                              void* d_out, int out_size) {
    const float* x     = (const float*)d_in[0];
    const float* probe = (const float*)d_in[1];
    const float* Wq    = (const float*)d_in[2];
    const float* bq    = (const float*)d_in[3];
    const float* Wk    = (const float*)d_in[4];
    const float* bk    = (const float*)d_in[5];
    const float* Wv    = (const float*)d_in[6];
    const float* bv    = (const float*)d_in[7];
    const float* Wo    = (const float*)d_in[8];
    const float* bo    = (const float*)d_in[9];
    float* out = (float*)d_out;

    k_prep_qh<<<HH, 256>>>(probe, Wq, bq);          // #1
    k_prep_wk<<<HH, 256>>>(Wk);                     // #2
    k_prep_sb<<<1, 384>>>(bk);                      // #3
    k_fused<<<dim3(NCHUNK, BB), 384>>>(x);          // #4  <- profiled
    k_combctx<<<dim3(BB, HH), 256>>>(Wv, bv);       // #5
    k_out<<<dim3(BB, 4), 192>>>(Wo, bo, out);       // #6
}

// round 6
// speedup vs baseline: 1.7751x; 1.0010x over previous
#include <cuda_runtime.h>

#define BB 32
#define SS 4096
#define CC 768
#define HH 12
#define DD 64
#define NCHUNK 43
#define SCHUNK 96

// ---- scratch (device globals; allocation is forbidden) ----
__device__ float g_qh[HH * DD];                               // scaled probe query
__device__ float g_wk[HH * CC];                               // folded key weights
__device__ float g_sbias[HH];                                 // qh . bk
__device__ float g_z[BB * NCHUNK * HH];                       // per-chunk expsum
__device__ float g_ypart[(size_t)BB * NCHUNK * HH * CC];      // per-chunk partial y
__device__ float g_ctx[BB * CC];                              // context (h,d flattened)

typedef unsigned long long u64;

__device__ __forceinline__ u64 pk2(float a, float b) {
    u64 r; asm("mov.b64 %0,{%1,%2};" : "=l"(r) : "f"(a), "f"(b)); return r;
}
__device__ __forceinline__ float2 up2(u64 v) {
    float2 r; asm("mov.b64 {%0,%1},%2;" : "=f"(r.x), "=f"(r.y) : "l"(v)); return r;
}
__device__ __forceinline__ void ffma2(u64& d, u64 a, u64 b) {
    asm("fma.rn.f32x2 %0,%1,%2,%0;" : "+l"(d) : "l"(a), "l"(b));
}
__device__ __forceinline__ u64 vadd2(u64 a, u64 b) {
    u64 r; asm("add.rn.f32x2 %0,%1,%2;" : "=l"(r) : "l"(a), "l"(b)); return r;
}

// ================= prep 1: qh = (probe @ Wq + bq)/8 =================
__global__ __launch_bounds__(256) void k_prep_qh(const float* __restrict__ probe,
                                                 const float* __restrict__ Wq,
                                                 const float* __restrict__ bq) {
    int h = blockIdx.x, t = threadIdx.x;
    __shared__ float red[4][DD];
    int d = t & 63, part = t >> 6;
    float a = 0.f;
    #pragma unroll 8
    for (int c = part; c < CC; c += 4)
        a = fmaf(probe[c], Wq[(size_t)c * CC + h * DD + d], a);
    red[part][d] = a;
    __syncthreads();
    if (t < DD)
        g_qh[h * DD + t] = (red[0][t] + red[1][t] + red[2][t] + red[3][t] + bq[h * DD + t]) * 0.125f;
}

// ================= prep 2: wk[h,c] = sum_d Wk[c,h,d]*qh[h,d] =================
__global__ __launch_bounds__(256) void k_prep_wk(const float* __restrict__ Wk) {
    int h = blockIdx.x, t = threadIdx.x;
    __shared__ float qs[DD];
    if (t < DD) qs[t] = g_qh[h * DD + t];
    __syncthreads();
    for (int c = t; c < CC; c += 256) {
        const float4* wr = (const float4*)(Wk + (size_t)c * CC + h * DD);
        float s = 0.f;
        #pragma unroll
        for (int j = 0; j < DD / 4; j++) {
            float4 wv = wr[j];
            const float4 qv = *(const float4*)(qs + 4 * j);
            s += wv.x * qv.x + wv.y * qv.y + wv.z * qv.z + wv.w * qv.w;
        }
        g_wk[h * CC + c] = s;
    }
}

// ================= prep 3: sbias[h] = qh[h,:].bk[h,:] =================
__global__ __launch_bounds__(384) void k_prep_sb(const float* __restrict__ bk) {
    int t = threadIdx.x, h = t >> 5, lane = t & 31;
    float a = g_qh[h * DD + lane] * bk[h * DD + lane]
            + g_qh[h * DD + 32 + lane] * bk[h * DD + 32 + lane];
    #pragma unroll
    for (int o = 16; o; o >>= 1) a += __shfl_xor_sync(~0u, a, o);
    if (lane == 0) g_sbias[h] = a;
}

// ================= fused: scores -> exp -> weighted accumulate (launch #4) ===========
// 384 threads, 2 blocks/SM (24 warps). Phase 1: warp pairs split heads 6+6,
// 4 rows/thread (acc[6][4]=48 regs). Phase 2: 4 cols/thread, 48-row halves
// (acc2[12][2]=48 regs). exp weights stored pre-duplicated (u64) in smem.
__global__ __launch_bounds__(384, 2) void k_fused(const float* __restrict__ x) {
    __shared__ __align__(16) float uS[HH * CC];      // wk (phase 1) / y stage (phase 2)
    __shared__ __align__(16) u64 scd[HH][SCHUNK];    // exp(score) duplicated, 9 KB
    __shared__ float zsh[HH];
    __shared__ float sbs[HH];

    int t = threadIdx.x, ch = blockIdx.x, b = blockIdx.y;
    int s0 = ch * SCHUNK;
    for (int i = t; i < HH * CC; i += 384) uS[i] = g_wk[i];
    if (t < HH) { sbs[t] = g_sbias[t]; zsh[t] = 0.f; }
    __syncthreads();

    int lane = t & 31, w = t >> 5, g = lane >> 3, q = lane & 7;
    const float* xb = x + (size_t)b * SS * CC;

    // ---- phase 1 ----
    {
        int p = w >> 1, h0 = (w & 1) * 6;
        int lbase = p * 16 + g;                        // local row = lbase + 4k
        const ulonglong2* xr[4];
        #pragma unroll
        for (int k = 0; k < 4; k++) {
            int row = s0 + lbase + 4 * k;
            int rc = row < SS ? row : SS - 1;
            xr[k] = (const ulonglong2*)(xb + (size_t)rc * CC) + q;
        }
        const ulonglong2* wq = (const ulonglong2*)uS + h0 * (CC / 4) + q;

        u64 acc[6][4];
        #pragma unroll
        for (int i = 0; i < 6; i++)
            #pragma unroll
            for (int k = 0; k < 4; k++) acc[i][k] = 0ull;

        #pragma unroll 4
        for (int j = 0; j < 24; j++) {
            ulonglong2 xv0 = xr[0][j * 8];
            ulonglong2 xv1 = xr[1][j * 8];
            ulonglong2 xv2 = xr[2][j * 8];
            ulonglong2 xv3 = xr[3][j * 8];
            #pragma unroll
            for (int i = 0; i < 6; i++) {
                ulonglong2 wv = wq[i * (CC / 4) + j * 8];
                ffma2(acc[i][0], xv0.x, wv.x); ffma2(acc[i][0], xv0.y, wv.y);
                ffma2(acc[i][1], xv1.x, wv.x); ffma2(acc[i][1], xv1.y, wv.y);
                ffma2(acc[i][2], xv2.x, wv.x); ffma2(acc[i][2], xv2.y, wv.y);
                ffma2(acc[i][3], xv3.x, wv.x); ffma2(acc[i][3], xv3.y, wv.y);
            }
        }
        #pragma unroll
        for (int i = 0; i < 6; i++) {
            float zt = 0.f;
            #pragma unroll
            for (int k = 0; k < 4; k++) {
                u64 v = acc[i][k];
                v = vadd2(v, __shfl_xor_sync(0xffffffffu, v, 4));
                v = vadd2(v, __shfl_xor_sync(0xffffffffu, v, 2));
                v = vadd2(v, __shfl_xor_sync(0xffffffffu, v, 1));
                if (q == 0) {
                    int lr = lbase + 4 * k;
                    float2 f = up2(v);
                    float e = (s0 + lr < SS) ? __expf(f.x + f.y + sbs[h0 + i]) : 0.f;
                    scd[h0 + i][lr] = pk2(e, e);
                    zt += e;
                }
            }
            float zq = (q == 0) ? zt : 0.f;
            zq += __shfl_xor_sync(0xffffffffu, zq, 8);
            zq += __shfl_xor_sync(0xffffffffu, zq, 16);
            if (lane == 0) atomicAdd(&zsh[h0 + i], zq);
        }
    }
    __syncthreads();
    if (t < HH) g_z[(b * NCHUNK + ch) * HH + t] = zsh[t];

    // ---- phase 2: y_part = sum_s p[h][s] * x[s,:] ----
    int half = t / 192, u = t - half * 192;            // cols 4u..4u+3
    int bs = half * 48;
    int rem = SS - (s0 + bs);
    int slim = rem < 0 ? 0 : (rem > 48 ? 48 : rem);    // always even
    const float* xp = xb + (size_t)(s0 + bs) * CC + 4 * u;

    u64 acc2[HH][2];
    #pragma unroll
    for (int h = 0; h < HH; h++) { acc2[h][0] = 0ull; acc2[h][1] = 0ull; }

    #pragma unroll 2
    for (int s2 = 0; s2 < slim / 2; s2++) {
        ulonglong2 x0 = *(const ulonglong2*)(xp + (size_t)(2 * s2) * CC);
        ulonglong2 x1 = *(const ulonglong2*)(xp + (size_t)(2 * s2 + 1) * CC);
        #pragma unroll
        for (int h = 0; h < HH; h++) {
            ulonglong2 pv = *(const ulonglong2*)&scd[h][bs + 2 * s2];
            ffma2(acc2[h][0], pv.x, x0.x); ffma2(acc2[h][1], pv.x, x0.y);
            ffma2(acc2[h][0], pv.y, x1.x); ffma2(acc2[h][1], pv.y, x1.y);
        }
    }

    // half 1 stages into uS (wk no longer needed); half 0 merges and writes
    __syncthreads();
    if (half == 1) {
        #pragma unroll
        for (int h = 0; h < HH; h++) {
            float2 l0 = up2(acc2[h][0]), l1 = up2(acc2[h][1]);
            *(float4*)(uS + h * CC + 4 * u) = make_float4(l0.x, l0.y, l1.x, l1.y);
        }
    }
    __syncthreads();
    if (half == 0) {
        float* yp = g_ypart + ((size_t)(b * NCHUNK + ch)) * (HH * CC);
        #pragma unroll
        for (int h = 0; h < HH; h++) {
            float2 l0 = up2(acc2[h][0]), l1 = up2(acc2[h][1]);
            float4 sv = *(const float4*)(uS + h * CC + 4 * u);
            *(float4*)(yp + h * CC + 4 * u) =
                make_float4(l0.x + sv.x, l0.y + sv.y, l1.x + sv.z, l1.y + sv.w);
        }
    }
}

// ================= combine + ctx: y = sum(ypart)/Z, ctx = y @ Wv + bv =================
__global__ __launch_bounds__(256) void k_combctx(const float* __restrict__ Wv,
                                                 const float* __restrict__ bv) {
    int b = blockIdx.x, h = blockIdx.y, t = threadIdx.x;
    __shared__ float ys[CC];
    __shared__ float red[4][DD];
    __shared__ float invZ_s;

    if (t < 32) {
        float z = 0.f;
        for (int c2 = t; c2 < NCHUNK; c2 += 32) z += g_z[(b * NCHUNK + c2) * HH + h];
        #pragma unroll
        for (int o = 16; o; o >>= 1) z += __shfl_xor_sync(~0u, z, o);
        if (t == 0) invZ_s = 1.f / z;
    }
    __syncthreads();
    float invZ = invZ_s;

    #pragma unroll
    for (int i = 0; i < 3; i++) {
        int c = t + 256 * i;
        const float* base = g_ypart + (size_t)b * NCHUNK * HH * CC + h * CC + c;
        float a0 = 0.f, a1 = 0.f, a2 = 0.f, a3 = 0.f;
        #pragma unroll 4
        for (int chn = 0; chn < NCHUNK - 3; chn += 4) {
            a0 += base[(size_t)chn * HH * CC];
            a1 += base[(size_t)(chn + 1) * HH * CC];
            a2 += base[(size_t)(chn + 2) * HH * CC];
            a3 += base[(size_t)(chn + 3) * HH * CC];
        }
        for (int chn = NCHUNK & ~3; chn < NCHUNK; chn++)
            a0 += base[(size_t)chn * HH * CC];
        ys[c] = ((a0 + a1) + (a2 + a3)) * invZ;
    }
    __syncthreads();

    int d = t & 63, part = t >> 6;
    const float* wp = Wv + h * DD + d;
    float a0 = 0.f, a1 = 0.f;
    #pragma unroll 8
    for (int c = part; c < CC; c += 8) {
        a0 = fmaf(ys[c],     wp[(size_t)c * CC],       a0);
        a1 = fmaf(ys[c + 4], wp[(size_t)(c + 4) * CC], a1);
    }
    red[part][d] = a0 + a1;
    __syncthreads();
    if (t < DD)
        g_ctx[b * CC + h * DD + t] =
            red[0][t] + red[1][t] + red[2][t] + red[3][t] + bv[h * DD + t];
}

// ================= out: out[b,c'] = ctx[b,:] @ Wo + bo =================
__global__ __launch_bounds__(192) void k_out(const float* __restrict__ Wo,
                                             const float* __restrict__ bo,
                                             float* __restrict__ out) {
    int b = blockIdx.x, part = blockIdx.y, t = threadIdx.x;
    __shared__ float cs[CC];
    for (int i = t; i < CC; i += 192) cs[i] = g_ctx[b * CC + i];
    __syncthreads();
    int cp = part * 192 + t;
    const float* wp = Wo + cp;
    float a0 = 0.f, a1 = 0.f, a2 = 0.f, a3 = 0.f;
    #pragma unroll 8
    for (int o = 0; o < CC; o += 4) {
        a0 = fmaf(cs[o],     wp[(size_t)o * CC],       a0);
        a1 = fmaf(cs[o + 1], wp[(size_t)(o + 1) * CC], a1);
        a2 = fmaf(cs[o + 2], wp[(size_t)(o + 2) * CC], a2);
        a3 = fmaf(cs[o + 3], wp[(size_t)(o + 3) * CC], a3);
    }
    out[(size_t)b * CC + cp] = (a0 + a1) + (a2 + a3) + bo[cp];
}

extern "C" void kernel_launch(void* const* d_in, const int* in_sizes, int n_in,
                              void* d_out, int out_size) {
    const float* x     = (const float*)d_in[0];
    const float* probe = (const float*)d_in[1];
    const float* Wq    = (const float*)d_in[2];
    const float* bq    = (const float*)d_in[3];
    const float* Wk    = (const float*)d_in[4];
    const float* bk    = (const float*)d_in[5];
    const float* Wv    = (const float*)d_in[6];
    const float* bv    = (const float*)d_in[7];
    const float* Wo    = (const float*)d_in[8];
    const float* bo    = (const float*)d_in[9];
    float* out = (float*)d_out;

    k_prep_qh<<<HH, 256>>>(probe, Wq, bq);          // #1
    k_prep_wk<<<HH, 256>>>(Wk);                     // #2
    k_prep_sb<<<1, 384>>>(bk);                      // #3
    k_fused<<<dim3(NCHUNK, BB), 384>>>(x);          // #4  <- profiled
    k_combctx<<<dim3(BB, HH), 256>>>(Wv, bv);       // #5
    k_out<<<dim3(BB, 4), 192>>>(Wo, bo, out);       // #6
}